// round 3
// baseline (speedup 1.0000x reference)
#include <cuda_runtime.h>
#include <cuda_bf16.h>
#include <math.h>

// ---------------- Problem constants ----------------
#define NNODES 50000
#define NEDGES 800000
#define DIN    256
#define DHID   128
#define DOUT   128
#define NEG_SLOPE 0.2f
#define EPSV  1e-16f

// ---------------- Scratch (device globals; no allocation allowed) ----------
__device__ float g_bufA[NNODES * 256];
__device__ float g_bufB[NNODES * 256];
__device__ float g_as[NNODES * 4];
__device__ float g_ad[NNODES * 4];
__device__ int   g_counts[NNODES + 1];
__device__ int   g_off[NNODES + 1];
__device__ int   g_cursor[NNODES];
__device__ int   g_srcs[NEDGES + NNODES];
__device__ int   g_flag[1];

// ---------------- CSR build ----------------
__global__ void k_reset(int n) {
    int i = blockIdx.x * blockDim.x + threadIdx.x;
    if (i == 0) g_flag[0] = 0;
    if (i < n) g_counts[i] = 1;   // self-loop pre-counted
}

// Read the first E int64 words. If the buffer is actually int32 (2E elems),
// that is exactly the whole buffer and packed pairs produce values >= 2^32
// (or negative), so at least one word falls out of [0, NNODES).
__global__ void k_detect(const long long* ei, int nwords) {
    int i = blockIdx.x * blockDim.x + threadIdx.x;
    if (i >= nwords) return;
    long long v = ei[i];
    if (v < 0 || v >= NNODES) g_flag[0] = 1;   // 1 => int32 layout
}

__device__ __forceinline__ int edge_val(const void* ei, int E, int which, int i, int is32) {
    if (is32) return ((const int*)ei)[which * E + i];
    return (int)((const long long*)ei)[which * E + i];
}

__global__ void k_count(const void* ei, int E) {
    int i = blockIdx.x * blockDim.x + threadIdx.x;
    if (i >= E) return;
    int is32 = g_flag[0];
    int d = edge_val(ei, E, 1, i, is32);
    atomicAdd(&g_counts[d], 1);
}

// Single-block scan, shfl-based warp scan + warp-sum scan.
__global__ void k_scan(int n) {
    __shared__ int warp_sums[32];
    __shared__ int s_running;
    int tid = threadIdx.x, lane = tid & 31, w = tid >> 5;
    if (tid == 0) { s_running = 0; g_off[0] = 0; }
    __syncthreads();
    for (int base = 0; base < n; base += 1024) {
        int i = base + tid;
        int v = (i < n) ? g_counts[i] : 0;
        int x = v;
        #pragma unroll
        for (int s = 1; s < 32; s <<= 1) {
            int t = __shfl_up_sync(0xffffffffu, x, s);
            if (lane >= s) x += t;
        }
        if (lane == 31) warp_sums[w] = x;
        __syncthreads();
        if (w == 0) {
            int y = warp_sums[lane];
            #pragma unroll
            for (int s = 1; s < 32; s <<= 1) {
                int t = __shfl_up_sync(0xffffffffu, y, s);
                if (lane >= s) y += t;
            }
            warp_sums[lane] = y;
        }
        __syncthreads();
        int incl = x + ((w > 0) ? warp_sums[w - 1] : 0);
        int run = s_running;
        if (i < n) {
            g_off[i + 1]  = run + incl;
            g_cursor[i]   = run + incl - v;
        }
        __syncthreads();
        if (tid == 1023) s_running = run + incl;
        __syncthreads();
    }
}

__global__ void k_scatter(const void* ei, int E, int n) {
    int i = blockIdx.x * blockDim.x + threadIdx.x;
    if (i < E) {
        int is32 = g_flag[0];
        int s = edge_val(ei, E, 0, i, is32);
        int d = edge_val(ei, E, 1, i, is32);
        int pos = atomicAdd(&g_cursor[d], 1);
        g_srcs[pos] = s;
    } else if (i < E + n) {
        int node = i - E;
        int pos = atomicAdd(&g_cursor[node], 1);
        g_srcs[pos] = node;
    }
}

// ---------------- Tiled SGEMM: C = act(A[M,K] @ B[K,N] + bias) ----------------
// BM=128, BN=128, BK=16, 256 threads, 8x8 per thread (strided by 16).
// Requires: K % 16 == 0, N % 128 == 0. M guarded.
template <int ACT> // 0 = none, 1 = relu
__global__ __launch_bounds__(256) void k_gemm(const float* __restrict__ A,
                                              const float* __restrict__ B,
                                              const float* __restrict__ bias,
                                              float* __restrict__ C,
                                              int M, int K, int N) {
    __shared__ float As[16][132];   // [k][m], padded (132 = 4*33, keeps f4 alignment)
    __shared__ float Bs[16][128];   // [k][n]
    int tid = threadIdx.x;
    int bm = blockIdx.x * 128;
    int bn = blockIdx.y * 128;
    int tr = tid >> 4;      // 0..15 -> rows tr + 16*i
    int tc = tid & 15;      // 0..15 -> cols tc + 16*j
    float acc[8][8] = {};

    // A-load decomposition: tile 128 rows x 16 cols = 512 float4 (4 f4 per row).
    int a_row  = tid >> 1;              // 0..127   (2 threads per row)
    int a_col4 = (tid & 1) * 2;         // 0 or 2   (each thread: 2 f4 = 8 floats)
    // B-load decomposition: tile 16 rows x 128 cols = 512 float4 (32 f4 per row).
    int b_row  = tid >> 4;              // 0..15
    int b_col4 = tid & 15;              // 0..15    (each thread: 2 f4, stride 16 f4)

    for (int k0 = 0; k0 < K; k0 += 16) {
        // Load A[bm + a_row, k0 + ...] -> As[k][m] (transposed)
        {
            int gr = bm + a_row;
            const float* ap = A + (size_t)gr * K + k0 + a_col4 * 4;
            float4 v0, v1;
            if (gr < M) {
                v0 = *(const float4*)(ap);
                v1 = *(const float4*)(ap + 4);
            } else {
                v0 = make_float4(0.f, 0.f, 0.f, 0.f);
                v1 = v0;
            }
            int c = a_col4 * 4;
            As[c + 0][a_row] = v0.x; As[c + 1][a_row] = v0.y;
            As[c + 2][a_row] = v0.z; As[c + 3][a_row] = v0.w;
            As[c + 4][a_row] = v1.x; As[c + 5][a_row] = v1.y;
            As[c + 6][a_row] = v1.z; As[c + 7][a_row] = v1.w;
        }
        // Load B[k0 + b_row, bn + ...] -> Bs[k][n]
        {
            const float* bp = B + (size_t)(k0 + b_row) * N + bn;
            *(float4*)&Bs[b_row][b_col4 * 4]      = *(const float4*)(bp + b_col4 * 4);
            *(float4*)&Bs[b_row][(b_col4 + 16) * 4] = *(const float4*)(bp + (b_col4 + 16) * 4);
        }
        __syncthreads();
        #pragma unroll
        for (int k = 0; k < 16; k++) {
            float ra[8], rb[8];
            #pragma unroll
            for (int i = 0; i < 8; i++) ra[i] = As[k][tr + 16 * i];
            #pragma unroll
            for (int j = 0; j < 8; j++) rb[j] = Bs[k][tc + 16 * j];
            #pragma unroll
            for (int i = 0; i < 8; i++)
                #pragma unroll
                for (int j = 0; j < 8; j++)
                    acc[i][j] = fmaf(ra[i], rb[j], acc[i][j]);
        }
        __syncthreads();
    }
    #pragma unroll
    for (int i = 0; i < 8; i++) {
        int gr = bm + tr + 16 * i;
        if (gr >= M) continue;
        #pragma unroll
        for (int j = 0; j < 8; j++) {
            int gc = bn + tc + 16 * j;
            float v = acc[i][j];
            if (bias) v += bias[gc];
            if (ACT == 1) v = fmaxf(v, 0.f);
            C[(size_t)gr * N + gc] = v;
        }
    }
}

// ---------------- Attention logits: per (node, head) dots ----------------
template <int H, int C>
__global__ __launch_bounds__(256) void k_alpha(const float* __restrict__ p,
                                               const float* __restrict__ a_s,
                                               const float* __restrict__ a_d) {
    int w = (blockIdx.x * blockDim.x + threadIdx.x) >> 5;
    int lane = threadIdx.x & 31;
    if (w >= NNODES * H) return;
    int node = w / H, h = w - node * H;
    const float* row = p + (size_t)node * (H * C) + h * C;
    float vs = 0.f, vd = 0.f;
    #pragma unroll
    for (int k = lane; k < C; k += 32) {
        float v = row[k];
        vs = fmaf(v, a_s[h * C + k], vs);
        vd = fmaf(v, a_d[h * C + k], vd);
    }
    #pragma unroll
    for (int o = 16; o; o >>= 1) {
        vs += __shfl_xor_sync(0xffffffffu, vs, o);
        vd += __shfl_xor_sync(0xffffffffu, vd, o);
    }
    if (lane == 0) { g_as[w] = vs; g_ad[w] = vd; }
}

// ---------------- GAT aggregation (one block per destination node) ---------
template <int H, int C, bool CONCAT, bool ELU>
__global__ __launch_bounds__(H * C) void k_gat_agg(const float* __restrict__ p,
                                                   const float* __restrict__ bias,
                                                   float* __restrict__ out) {
    constexpr int HC = H * C;
    constexpr int CHUNK = 32;
    __shared__ int   s_src[CHUNK];
    __shared__ float s_w[CHUNK * H];
    __shared__ float s_m[H];
    __shared__ float s_den[H];
    __shared__ float s_adv[H];
    __shared__ float s_red[HC];

    int node = blockIdx.x;
    int tid = threadIdx.x;
    int beg = g_off[node], end = g_off[node + 1];
    int w = tid >> 5, lane = tid & 31;

    if (tid < H) s_adv[tid] = g_ad[node * H + tid];
    __syncthreads();

    // Pass A: per-head max (warp w handles head w)
    if (w < H) {
        float ad_h = s_adv[w];
        float mm = -INFINITY;
        for (int e = beg + lane; e < end; e += 32) {
            float z = g_as[g_srcs[e] * H + w] + ad_h;
            z = (z > 0.f) ? z : NEG_SLOPE * z;
            mm = fmaxf(mm, z);
        }
        #pragma unroll
        for (int o = 16; o; o >>= 1) mm = fmaxf(mm, __shfl_xor_sync(0xffffffffu, mm, o));
        if (lane == 0) s_m[w] = mm;
    }
    __syncthreads();

    // Pass B: per-head denominator
    if (w < H) {
        float ad_h = s_adv[w];
        float mm = s_m[w];
        float den = 0.f;
        for (int e = beg + lane; e < end; e += 32) {
            float z = g_as[g_srcs[e] * H + w] + ad_h;
            z = (z > 0.f) ? z : NEG_SLOPE * z;
            den += __expf(z - mm);
        }
        #pragma unroll
        for (int o = 16; o; o >>= 1) den += __shfl_xor_sync(0xffffffffu, den, o);
        if (lane == 0) s_den[w] = den + EPSV;
    }
    __syncthreads();

    // Pass C: chunked weighted accumulation
    float acc = 0.f;
    const int h_of_tid = tid / C;
    for (int cb = beg; cb < end; cb += CHUNK) {
        int len = min(CHUNK, end - cb);
        if (tid < len) s_src[tid] = g_srcs[cb + tid];
        __syncthreads();
        if (tid < len * H) {
            int e_i = tid / H, h = tid - e_i * H;
            int s = s_src[e_i];
            float z = g_as[s * H + h] + s_adv[h];
            z = (z > 0.f) ? z : NEG_SLOPE * z;
            s_w[tid] = __expf(z - s_m[h]) / s_den[h];
        }
        __syncthreads();
        int e = 0;
        for (; e + 4 <= len; e += 4) {
            float v0 = p[(size_t)s_src[e + 0] * HC + tid];
            float v1 = p[(size_t)s_src[e + 1] * HC + tid];
            float v2 = p[(size_t)s_src[e + 2] * HC + tid];
            float v3 = p[(size_t)s_src[e + 3] * HC + tid];
            acc = fmaf(v0, s_w[(e + 0) * H + h_of_tid], acc);
            acc = fmaf(v1, s_w[(e + 1) * H + h_of_tid], acc);
            acc = fmaf(v2, s_w[(e + 2) * H + h_of_tid], acc);
            acc = fmaf(v3, s_w[(e + 3) * H + h_of_tid], acc);
        }
        for (; e < len; e++) {
            float v = p[(size_t)s_src[e] * HC + tid];
            acc = fmaf(v, s_w[e * H + h_of_tid], acc);
        }
        __syncthreads();
    }

    if (CONCAT) {
        float v = acc + bias[tid];
        if (ELU) v = (v > 0.f) ? v : expm1f(v);
        out[(size_t)node * HC + tid] = v;
    } else {
        s_red[tid] = acc;
        __syncthreads();
        if (tid < C) {
            float v = 0.f;
            #pragma unroll
            for (int h = 0; h < H; h++) v += s_red[h * C + tid];
            v = v * (1.f / H) + bias[tid];
            if (ELU) v = (v > 0.f) ? v : expm1f(v);
            out[(size_t)node * C + tid] = v;
        }
    }
}

// ---------------- Launch ----------------
extern "C" void kernel_launch(void* const* d_in, const int* in_sizes, int n_in,
                              void* d_out, int out_size) {
    const float* x     = (const float*)d_in[0];
    const void*  ei    = d_in[1];
    const float* W1    = (const float*)d_in[2];
    const float* b1    = (const float*)d_in[3];
    const float* W2    = (const float*)d_in[4];
    const float* b2    = (const float*)d_in[5];
    const float* g1W   = (const float*)d_in[6];
    const float* g1as  = (const float*)d_in[7];
    const float* g1ad  = (const float*)d_in[8];
    const float* g1b   = (const float*)d_in[9];
    const float* g2W   = (const float*)d_in[10];
    const float* g2as  = (const float*)d_in[11];
    const float* g2ad  = (const float*)d_in[12];
    const float* g2b   = (const float*)d_in[13];
    const float* g3W   = (const float*)d_in[14];
    const float* g3as  = (const float*)d_in[15];
    const float* g3ad  = (const float*)d_in[16];
    const float* g3b   = (const float*)d_in[17];
    float* out = (float*)d_out;

    float* bufA; float* bufB;
    cudaGetSymbolAddress((void**)&bufA, g_bufA);
    cudaGetSymbolAddress((void**)&bufB, g_bufB);

    const int M = NNODES;
    const int E = in_sizes[1] / 2;   // element count / 2 for either dtype

    // ---- CSR build (by destination) ----
    k_reset<<<(M + 255) / 256, 256>>>(M);
    k_detect<<<(E + 255) / 256, 256>>>((const long long*)ei, E);
    k_count<<<(E + 255) / 256, 256>>>(ei, E);
    k_scan<<<1, 1024>>>(M);
    k_scatter<<<(E + M + 255) / 256, 256>>>(ei, E, M);

    dim3 blk(256);
    const int GM = (M + 127) / 128;
    // ---- MLP ----
    { dim3 g(GM, DHID / 128);
      k_gemm<1><<<g, blk>>>(x, W1, b1, bufA, M, DIN, DHID); }        // h1 -> A
    { dim3 g(GM, DHID / 128);
      k_gemm<1><<<g, blk>>>(bufA, W2, b2, bufB, M, DHID, DHID); }    // h2 -> B

    // ---- GAT layer 1: H=4, C=64, concat, elu ----
    { dim3 g(GM, 256 / 128);
      k_gemm<0><<<g, blk>>>(bufB, g1W, nullptr, bufA, M, DHID, 256); } // p1 -> A
    k_alpha<4, 64><<<(M * 4 * 32 + 255) / 256, 256>>>(bufA, g1as, g1ad);
    k_gat_agg<4, 64, true, true><<<M, 256>>>(bufA, g1b, bufB);          // h3 -> B

    // ---- GAT layer 2: H=2, C=128, mean, elu ----
    { dim3 g(GM, 256 / 128);
      k_gemm<0><<<g, blk>>>(bufB, g2W, nullptr, bufA, M, 256, 256); } // p2 -> A
    k_alpha<2, 128><<<(M * 2 * 32 + 255) / 256, 256>>>(bufA, g2as, g2ad);
    k_gat_agg<2, 128, false, true><<<M, 256>>>(bufA, g2b, bufB);        // h4 -> B

    // ---- GAT layer 3: H=1, C=128, mean (identity), no elu ----
    { dim3 g(GM, DOUT / 128);
      k_gemm<0><<<g, blk>>>(bufB, g3W, nullptr, bufA, M, DOUT, DOUT); } // p3 -> A
    k_alpha<1, 128><<<(M * 1 * 32 + 255) / 256, 256>>>(bufA, g3as, g3ad);
    k_gat_agg<1, 128, false, false><<<M, 128>>>(bufA, g3b, out);
}

// round 6
// speedup vs baseline: 1.1804x; 1.1804x over previous
#include <cuda_runtime.h>
#include <cuda_bf16.h>
#include <math.h>

// ---------------- Problem constants ----------------
#define NNODES 50000
#define NEDGES 800000
#define DIN    256
#define DHID   128
#define DOUT   128
#define NEG_SLOPE 0.2f
#define EPSV  1e-16f
#define NPART ((NNODES + 1023) / 1024)   // 49

// ---------------- Scratch (device globals; no allocation allowed) ----------
// __align__(16): float4 paths require 16B base alignment (HW traps otherwise).
__device__ __align__(16) float g_bufA[NNODES * 256];
__device__ __align__(16) float g_bufB[NNODES * 256];
__device__ __align__(16) float g_as[NNODES * 4];
__device__ __align__(16) float g_ad[NNODES * 4];
__device__ int   g_counts[NNODES + 1];
__device__ int   g_off[NNODES + 1];
__device__ int   g_cursor[NNODES];
__device__ int   g_srcs[NEDGES + NNODES];
__device__ int   g_part[64];
__device__ int   g_flag[1];

// ---------------- CSR build ----------------
__global__ void k_reset(int n) {
    int i = blockIdx.x * blockDim.x + threadIdx.x;
    if (i == 0) g_flag[0] = 0;
    if (i < n) g_counts[i] = 1;   // self-loop pre-counted
}

// Read the first E int64 words. If the buffer is actually int32 (2E elems),
// packed pairs produce values out of [0, NNODES) somewhere.
__global__ void k_detect(const long long* ei, int nwords) {
    int i = blockIdx.x * blockDim.x + threadIdx.x;
    if (i >= nwords) return;
    long long v = ei[i];
    if (v < 0 || v >= NNODES) g_flag[0] = 1;   // 1 => int32 layout
}

__device__ __forceinline__ int edge_val(const void* ei, int E, int which, int i, int is32) {
    if (is32) return ((const int*)ei)[which * E + i];
    return (int)((const long long*)ei)[which * E + i];
}

__global__ void k_count(const void* ei, int E) {
    int i = blockIdx.x * blockDim.x + threadIdx.x;
    if (i >= E) return;
    int is32 = g_flag[0];
    int d = edge_val(ei, E, 1, i, is32);
    atomicAdd(&g_counts[d], 1);
}

// ---- Hierarchical scan: local scan -> scan of partials -> apply ----
__global__ void k_scan1(int n) {   // NPART blocks x 1024
    __shared__ int warp_sums[32];
    int tid = threadIdx.x, lane = tid & 31, w = tid >> 5;
    int i = blockIdx.x * 1024 + tid;
    int v = (i < n) ? g_counts[i] : 0;
    int x = v;
    #pragma unroll
    for (int s = 1; s < 32; s <<= 1) {
        int t = __shfl_up_sync(0xffffffffu, x, s);
        if (lane >= s) x += t;
    }
    if (lane == 31) warp_sums[w] = x;
    __syncthreads();
    if (w == 0) {
        int y = warp_sums[lane];
        #pragma unroll
        for (int s = 1; s < 32; s <<= 1) {
            int t = __shfl_up_sync(0xffffffffu, y, s);
            if (lane >= s) y += t;
        }
        warp_sums[lane] = y;
    }
    __syncthreads();
    int incl = x + ((w > 0) ? warp_sums[w - 1] : 0);
    if (i < n) g_off[i + 1] = incl;                 // block-local inclusive
    if (tid == 1023) g_part[blockIdx.x] = incl;     // block total
}

__global__ void k_scan2() {   // 1 block, 64 threads (NPART <= 64)
    __shared__ int ws[2];
    int tid = threadIdx.x, lane = tid & 31, w = tid >> 5;
    int x = (tid < NPART) ? g_part[tid] : 0;
    #pragma unroll
    for (int s = 1; s < 32; s <<= 1) {
        int t = __shfl_up_sync(0xffffffffu, x, s);
        if (lane >= s) x += t;
    }
    if (lane == 31) ws[w] = x;
    __syncthreads();
    if (w == 1) x += ws[0];
    g_part[tid] = x;   // inclusive partial sums
}

__global__ void k_scan3(int n) {   // NPART blocks x 1024
    int tid = threadIdx.x;
    int b = blockIdx.x;
    int i = b * 1024 + tid;
    if (i >= n) return;
    int base = (b > 0) ? g_part[b - 1] : 0;
    int incl = g_off[i + 1] + base;
    g_off[i + 1] = incl;
    g_cursor[i]  = incl - g_counts[i];
    if (i == 0) g_off[0] = 0;
}

__global__ void k_scatter(const void* ei, int E, int n) {
    int i = blockIdx.x * blockDim.x + threadIdx.x;
    if (i < E) {
        int is32 = g_flag[0];
        int s = edge_val(ei, E, 0, i, is32);
        int d = edge_val(ei, E, 1, i, is32);
        int pos = atomicAdd(&g_cursor[d], 1);
        g_srcs[pos] = s;
    } else if (i < E + n) {
        int node = i - E;
        int pos = atomicAdd(&g_cursor[node], 1);
        g_srcs[pos] = node;
    }
}

// ---------------- Tiled SGEMM: C = act(A[M,K] @ B[K,N] + bias) ----------------
// BM=128, BN=128, BK=16, 256 threads, 8x8 per thread, register double-buffered.
// Requires: K % 16 == 0, N % 128 == 0. M guarded. A,B,C must be 16B-aligned.
template <int ACT> // 0 = none, 1 = relu
__global__ __launch_bounds__(256, 2) void k_gemm(const float* __restrict__ A,
                                                 const float* __restrict__ B,
                                                 const float* __restrict__ bias,
                                                 float* __restrict__ C,
                                                 int M, int K, int N) {
    __shared__ __align__(16) float As[16][132];   // [k][m], padded
    __shared__ __align__(16) float Bs[16][128];   // [k][n]
    int tid = threadIdx.x;
    int bm = blockIdx.x * 128;
    int bn = blockIdx.y * 128;
    int tr = tid >> 4;      // rows tr + 16*i
    int tc = tid & 15;      // cols tc + 16*j
    float acc[8][8] = {};

    int a_row  = tid >> 1;              // 0..127
    int a_col4 = (tid & 1) * 2;         // 0 or 2 (2 float4 per thread)
    int b_row  = tid >> 4;              // 0..15
    int b_col4 = tid & 15;              // 0..15 (2 float4, stride 16)

    const bool a_ok = (bm + a_row) < M;
    const float* aptr = A + (size_t)(bm + a_row) * K + a_col4 * 4;
    const float* bptr = B + (size_t)b_row * N + bn;

    float4 av0, av1, bv0, bv1;
    const float4 zero4 = make_float4(0.f, 0.f, 0.f, 0.f);

    // prefetch k0 = 0
    av0 = a_ok ? *(const float4*)(aptr)     : zero4;
    av1 = a_ok ? *(const float4*)(aptr + 4) : zero4;
    bv0 = *(const float4*)(bptr + b_col4 * 4);
    bv1 = *(const float4*)(bptr + (b_col4 + 16) * 4);

    for (int k0 = 0; k0 < K; k0 += 16) {
        // stage registers -> smem
        {
            int c = a_col4 * 4;
            As[c + 0][a_row] = av0.x; As[c + 1][a_row] = av0.y;
            As[c + 2][a_row] = av0.z; As[c + 3][a_row] = av0.w;
            As[c + 4][a_row] = av1.x; As[c + 5][a_row] = av1.y;
            As[c + 6][a_row] = av1.z; As[c + 7][a_row] = av1.w;
            *(float4*)&Bs[b_row][b_col4 * 4]        = bv0;
            *(float4*)&Bs[b_row][(b_col4 + 16) * 4] = bv1;
        }
        __syncthreads();
        // prefetch next tile (overlaps with compute below)
        if (k0 + 16 < K) {
            const float* ap = aptr + k0 + 16;
            av0 = a_ok ? *(const float4*)(ap)     : zero4;
            av1 = a_ok ? *(const float4*)(ap + 4) : zero4;
            const float* bp = bptr + (size_t)(k0 + 16) * N;
            bv0 = *(const float4*)(bp + b_col4 * 4);
            bv1 = *(const float4*)(bp + (b_col4 + 16) * 4);
        }
        #pragma unroll
        for (int k = 0; k < 16; k++) {
            float ra[8], rb[8];
            #pragma unroll
            for (int i = 0; i < 8; i++) ra[i] = As[k][tr + 16 * i];
            #pragma unroll
            for (int j = 0; j < 8; j++) rb[j] = Bs[k][tc + 16 * j];
            #pragma unroll
            for (int i = 0; i < 8; i++)
                #pragma unroll
                for (int j = 0; j < 8; j++)
                    acc[i][j] = fmaf(ra[i], rb[j], acc[i][j]);
        }
        __syncthreads();
    }
    #pragma unroll
    for (int i = 0; i < 8; i++) {
        int gr = bm + tr + 16 * i;
        if (gr >= M) continue;
        #pragma unroll
        for (int j = 0; j < 8; j++) {
            int gc = bn + tc + 16 * j;
            float v = acc[i][j];
            if (bias) v += bias[gc];
            if (ACT == 1) v = fmaxf(v, 0.f);
            C[(size_t)gr * N + gc] = v;
        }
    }
}

// ---------------- Attention logits: per (node, head) dots ----------------
template <int H, int C>
__global__ __launch_bounds__(256) void k_alpha(const float* __restrict__ p,
                                               const float* __restrict__ a_s,
                                               const float* __restrict__ a_d) {
    int w = (blockIdx.x * blockDim.x + threadIdx.x) >> 5;
    int lane = threadIdx.x & 31;
    if (w >= NNODES * H) return;
    int node = w / H, h = w - node * H;
    const float* row = p + (size_t)node * (H * C) + h * C;
    float vs = 0.f, vd = 0.f;
    #pragma unroll
    for (int k = lane; k < C; k += 32) {
        float v = row[k];
        vs = fmaf(v, a_s[h * C + k], vs);
        vd = fmaf(v, a_d[h * C + k], vd);
    }
    #pragma unroll
    for (int o = 16; o; o >>= 1) {
        vs += __shfl_xor_sync(0xffffffffu, vs, o);
        vd += __shfl_xor_sync(0xffffffffu, vd, o);
    }
    if (lane == 0) { g_as[w] = vs; g_ad[w] = vd; }
}

// ---------------- GAT aggregation (one block per destination node) ---------
// Threads = H*C. Pass 1: online softmax stats (one traversal). Pass 2: chunked
// float4 gathers, 4 edge-groups in parallel, cross-group smem reduce.
template <int H, int C, bool CONCAT, bool ELU>
__global__ __launch_bounds__(H * C) void k_gat_agg(const float* __restrict__ p,
                                                   const float* __restrict__ bias,
                                                   float* __restrict__ out) {
    constexpr int HC = H * C;
    constexpr int V = HC / 4;        // float4s per row
    constexpr int GROUPS = 4;        // HC threads = 4 * V
    constexpr int CHUNK = 32;
    __shared__ int   s_src[CHUNK];
    __shared__ float s_w[CHUNK * H];
    __shared__ float s_m[H];
    __shared__ float s_den[H];
    __shared__ float s_adv[H];
    __shared__ __align__(16) float s_red[GROUPS * HC];

    int node = blockIdx.x;
    int tid = threadIdx.x;
    int beg = g_off[node], end = g_off[node + 1];
    int w = tid >> 5, lane = tid & 31;

    if (tid < H) s_adv[tid] = g_ad[node * H + tid];
    __syncthreads();

    // Pass 1: online softmax (max + denom in one traversal), warp w = head w
    if (w < H) {
        float ad_h = s_adv[w];
        float m_l = -1e30f, d_l = 0.f;
        for (int e = beg + lane; e < end; e += 32) {
            float z = g_as[g_srcs[e] * H + w] + ad_h;
            z = (z > 0.f) ? z : NEG_SLOPE * z;
            float mo = fmaxf(m_l, z);
            d_l = d_l * __expf(m_l - mo) + __expf(z - mo);
            m_l = mo;
        }
        #pragma unroll
        for (int o = 16; o; o >>= 1) {
            float m2 = __shfl_xor_sync(0xffffffffu, m_l, o);
            float d2 = __shfl_xor_sync(0xffffffffu, d_l, o);
            float mo = fmaxf(m_l, m2);
            d_l = d_l * __expf(m_l - mo) + d2 * __expf(m2 - mo);
            m_l = mo;
        }
        if (lane == 0) { s_m[w] = m_l; s_den[w] = d_l + EPSV; }
    }
    __syncthreads();

    // Pass 2: chunked weighted accumulation (float4, 4 edge-groups)
    const int grp = tid / V;          // 0..3
    const int q   = tid - grp * V;    // float4 index within row
    const int h_of = (4 * q) / C;     // head of this thread's channels
    float4 acc = make_float4(0.f, 0.f, 0.f, 0.f);

    for (int cb = beg; cb < end; cb += CHUNK) {
        int len = min(CHUNK, end - cb);
        if (tid < len) s_src[tid] = g_srcs[cb + tid];
        __syncthreads();
        if (tid < len * H) {
            int e_i = tid / H, h = tid - e_i * H;
            int s = s_src[e_i];
            float z = g_as[s * H + h] + s_adv[h];
            z = (z > 0.f) ? z : NEG_SLOPE * z;
            s_w[tid] = __expf(z - s_m[h]) / s_den[h];
        }
        __syncthreads();
        int e = grp;
        for (; e + GROUPS < len; e += 2 * GROUPS) {
            int s0 = s_src[e], s1 = s_src[e + GROUPS];
            float4 v0 = *(const float4*)&p[(size_t)s0 * HC + 4 * q];
            float4 v1 = *(const float4*)&p[(size_t)s1 * HC + 4 * q];
            float w0 = s_w[e * H + h_of];
            float w1 = s_w[(e + GROUPS) * H + h_of];
            acc.x = fmaf(v0.x, w0, acc.x); acc.y = fmaf(v0.y, w0, acc.y);
            acc.z = fmaf(v0.z, w0, acc.z); acc.w = fmaf(v0.w, w0, acc.w);
            acc.x = fmaf(v1.x, w1, acc.x); acc.y = fmaf(v1.y, w1, acc.y);
            acc.z = fmaf(v1.z, w1, acc.z); acc.w = fmaf(v1.w, w1, acc.w);
        }
        if (e < len) {
            int s0 = s_src[e];
            float4 v0 = *(const float4*)&p[(size_t)s0 * HC + 4 * q];
            float w0 = s_w[e * H + h_of];
            acc.x = fmaf(v0.x, w0, acc.x); acc.y = fmaf(v0.y, w0, acc.y);
            acc.z = fmaf(v0.z, w0, acc.z); acc.w = fmaf(v0.w, w0, acc.w);
        }
        __syncthreads();
    }

    // Cross-group reduce
    *(float4*)&s_red[grp * HC + 4 * q] = acc;
    __syncthreads();

    if (CONCAT) {
        float v = 0.f;
        #pragma unroll
        for (int g = 0; g < GROUPS; g++) v += s_red[g * HC + tid];
        v += bias[tid];
        if (ELU) v = (v > 0.f) ? v : expm1f(v);
        out[(size_t)node * HC + tid] = v;
    } else {
        if (tid < C) {
            float v = 0.f;
            #pragma unroll
            for (int g = 0; g < GROUPS; g++)
                #pragma unroll
                for (int h = 0; h < H; h++)
                    v += s_red[g * HC + h * C + tid];
            v = v * (1.f / H) + bias[tid];
            if (ELU) v = (v > 0.f) ? v : expm1f(v);
            out[(size_t)node * C + tid] = v;
        }
    }
}

// ---------------- Launch ----------------
extern "C" void kernel_launch(void* const* d_in, const int* in_sizes, int n_in,
                              void* d_out, int out_size) {
    const float* x     = (const float*)d_in[0];
    const void*  ei    = d_in[1];
    const float* W1    = (const float*)d_in[2];
    const float* b1    = (const float*)d_in[3];
    const float* W2    = (const float*)d_in[4];
    const float* b2    = (const float*)d_in[5];
    const float* g1W   = (const float*)d_in[6];
    const float* g1as  = (const float*)d_in[7];
    const float* g1ad  = (const float*)d_in[8];
    const float* g1b   = (const float*)d_in[9];
    const float* g2W   = (const float*)d_in[10];
    const float* g2as  = (const float*)d_in[11];
    const float* g2ad  = (const float*)d_in[12];
    const float* g2b   = (const float*)d_in[13];
    const float* g3W   = (const float*)d_in[14];
    const float* g3as  = (const float*)d_in[15];
    const float* g3ad  = (const float*)d_in[16];
    const float* g3b   = (const float*)d_in[17];
    float* out = (float*)d_out;

    float* bufA; float* bufB;
    cudaGetSymbolAddress((void**)&bufA, g_bufA);
    cudaGetSymbolAddress((void**)&bufB, g_bufB);

    const int M = NNODES;
    const int E = in_sizes[1] / 2;   // element count / 2 for either dtype

    // ---- CSR build (by destination) ----
    k_reset<<<(M + 255) / 256, 256>>>(M);
    k_detect<<<(E + 255) / 256, 256>>>((const long long*)ei, E);
    k_count<<<(E + 255) / 256, 256>>>(ei, E);
    k_scan1<<<NPART, 1024>>>(M);
    k_scan2<<<1, 64>>>();
    k_scan3<<<NPART, 1024>>>(M);
    k_scatter<<<(E + M + 255) / 256, 256>>>(ei, E, M);

    dim3 blk(256);
    const int GM = (M + 127) / 128;
    // ---- MLP ----
    { dim3 g(GM, DHID / 128);
      k_gemm<1><<<g, blk>>>(x, W1, b1, bufA, M, DIN, DHID); }        // h1 -> A
    { dim3 g(GM, DHID / 128);
      k_gemm<1><<<g, blk>>>(bufA, W2, b2, bufB, M, DHID, DHID); }    // h2 -> B

    // ---- GAT layer 1: H=4, C=64, concat, elu ----
    { dim3 g(GM, 256 / 128);
      k_gemm<0><<<g, blk>>>(bufB, g1W, nullptr, bufA, M, DHID, 256); } // p1 -> A
    k_alpha<4, 64><<<(M * 4 * 32 + 255) / 256, 256>>>(bufA, g1as, g1ad);
    k_gat_agg<4, 64, true, true><<<M, 256>>>(bufA, g1b, bufB);          // h3 -> B

    // ---- GAT layer 2: H=2, C=128, mean, elu ----
    { dim3 g(GM, 256 / 128);
      k_gemm<0><<<g, blk>>>(bufB, g2W, nullptr, bufA, M, 256, 256); } // p2 -> A
    k_alpha<2, 128><<<(M * 2 * 32 + 255) / 256, 256>>>(bufA, g2as, g2ad);
    k_gat_agg<2, 128, false, true><<<M, 256>>>(bufA, g2b, bufB);        // h4 -> B

    // ---- GAT layer 3: H=1, C=128, mean (identity), no elu ----
    { dim3 g(GM, DOUT / 128);
      k_gemm<0><<<g, blk>>>(bufB, g3W, nullptr, bufA, M, DOUT, DOUT); } // p3 -> A
    k_alpha<1, 128><<<(M * 1 * 32 + 255) / 256, 256>>>(bufA, g3as, g3ad);
    k_gat_agg<1, 128, false, false><<<M, 128>>>(bufA, g3b, out);
}

// round 7
// speedup vs baseline: 1.5927x; 1.3493x over previous
#include <cuda_runtime.h>
#include <cuda_bf16.h>
#include <math.h>

// ---------------- Problem constants ----------------
#define NNODES 50000
#define NEDGES 800000
#define DIN    256
#define DHID   128
#define DOUT   128
#define NEG_SLOPE 0.2f
#define EPSV  1e-16f
#define NPART ((NNODES + 1023) / 1024)   // 49

// Weight arena offsets (elements)
#define OFF_W1 0         // 256*128
#define OFF_W2 32768     // 128*128
#define OFF_G1 49152     // 128*256
#define OFF_G2 81920     // 256*256
#define OFF_G3 147456    // 128*128
#define W_TOTAL 163840

// ---------------- Scratch (device globals; no allocation allowed) ----------
__device__ __align__(16) float g_bufA[NNODES * 256];
__device__ __align__(16) float g_bufB[NNODES * 256];
__device__ __align__(16) float g_as[NNODES * 4];
__device__ __align__(16) float g_ad[NNODES * 4];
__device__ __align__(16) __nv_bfloat16 g_wh[W_TOTAL];
__device__ __align__(16) __nv_bfloat16 g_wl[W_TOTAL];
__device__ int   g_counts[NNODES + 1];
__device__ int   g_off[NNODES + 1];
__device__ int   g_cursor[NNODES];
__device__ int   g_srcs[NEDGES + NNODES];
__device__ int   g_part[64];
__device__ int   g_flag[1];

// ---------------- CSR build ----------------
__global__ void k_reset(int n) {
    int i = blockIdx.x * blockDim.x + threadIdx.x;
    if (i == 0) g_flag[0] = 0;
    if (i < n) g_counts[i] = 1;   // self-loop pre-counted
}

__global__ void k_detect(const long long* ei, int nwords) {
    int i = blockIdx.x * blockDim.x + threadIdx.x;
    if (i >= nwords) return;
    long long v = ei[i];
    if (v < 0 || v >= NNODES) g_flag[0] = 1;   // 1 => int32 layout
}

__device__ __forceinline__ int edge_val(const void* ei, int E, int which, int i, int is32) {
    if (is32) return ((const int*)ei)[which * E + i];
    return (int)((const long long*)ei)[which * E + i];
}

__global__ void k_count(const void* ei, int E) {
    int i = blockIdx.x * blockDim.x + threadIdx.x;
    if (i >= E) return;
    int is32 = g_flag[0];
    int d = edge_val(ei, E, 1, i, is32);
    atomicAdd(&g_counts[d], 1);
}

__global__ void k_scan1(int n) {
    __shared__ int warp_sums[32];
    int tid = threadIdx.x, lane = tid & 31, w = tid >> 5;
    int i = blockIdx.x * 1024 + tid;
    int v = (i < n) ? g_counts[i] : 0;
    int x = v;
    #pragma unroll
    for (int s = 1; s < 32; s <<= 1) {
        int t = __shfl_up_sync(0xffffffffu, x, s);
        if (lane >= s) x += t;
    }
    if (lane == 31) warp_sums[w] = x;
    __syncthreads();
    if (w == 0) {
        int y = warp_sums[lane];
        #pragma unroll
        for (int s = 1; s < 32; s <<= 1) {
            int t = __shfl_up_sync(0xffffffffu, y, s);
            if (lane >= s) y += t;
        }
        warp_sums[lane] = y;
    }
    __syncthreads();
    int incl = x + ((w > 0) ? warp_sums[w - 1] : 0);
    if (i < n) g_off[i + 1] = incl;
    if (tid == 1023) g_part[blockIdx.x] = incl;
}

__global__ void k_scan2() {
    __shared__ int ws[2];
    int tid = threadIdx.x, lane = tid & 31, w = tid >> 5;
    int x = (tid < NPART) ? g_part[tid] : 0;
    #pragma unroll
    for (int s = 1; s < 32; s <<= 1) {
        int t = __shfl_up_sync(0xffffffffu, x, s);
        if (lane >= s) x += t;
    }
    if (lane == 31) ws[w] = x;
    __syncthreads();
    if (w == 1) x += ws[0];
    g_part[tid] = x;
}

__global__ void k_scan3(int n) {
    int tid = threadIdx.x;
    int b = blockIdx.x;
    int i = b * 1024 + tid;
    if (i >= n) return;
    int base = (b > 0) ? g_part[b - 1] : 0;
    int incl = g_off[i + 1] + base;
    g_off[i + 1] = incl;
    g_cursor[i]  = incl - g_counts[i];
    if (i == 0) g_off[0] = 0;
}

__global__ void k_scatter(const void* ei, int E, int n) {
    int i = blockIdx.x * blockDim.x + threadIdx.x;
    if (i < E) {
        int is32 = g_flag[0];
        int s = edge_val(ei, E, 0, i, is32);
        int d = edge_val(ei, E, 1, i, is32);
        int pos = atomicAdd(&g_cursor[d], 1);
        g_srcs[pos] = s;
    } else if (i < E + n) {
        int node = i - E;
        int pos = atomicAdd(&g_cursor[node], 1);
        g_srcs[pos] = node;
    }
}

// ---------------- Weight preconversion: f32 -> bf16 hi/lo ----------------
__global__ void k_cvtw(const float* __restrict__ src, __nv_bfloat16* __restrict__ h,
                       __nv_bfloat16* __restrict__ l, int n) {
    int i = blockIdx.x * blockDim.x + threadIdx.x;
    if (i >= n) return;
    float x = src[i];
    __nv_bfloat16 hb = __float2bfloat16(x);
    h[i] = hb;
    l[i] = __float2bfloat16(x - __bfloat162float(hb));
}

// ---------------- Tensor-core GEMM (bf16 split-precision) ----------------
__device__ __forceinline__ void ldsm_x4(unsigned addr, unsigned &r0, unsigned &r1,
                                        unsigned &r2, unsigned &r3) {
    asm volatile("ldmatrix.sync.aligned.m8n8.x4.shared.b16 {%0,%1,%2,%3}, [%4];"
                 : "=r"(r0), "=r"(r1), "=r"(r2), "=r"(r3) : "r"(addr));
}
__device__ __forceinline__ void ldsm_x2t(unsigned addr, unsigned &r0, unsigned &r1) {
    asm volatile("ldmatrix.sync.aligned.m8n8.x2.trans.shared.b16 {%0,%1}, [%2];"
                 : "=r"(r0), "=r"(r1) : "r"(addr));
}
__device__ __forceinline__ void mma_bf16(float* d, unsigned a0, unsigned a1,
                                         unsigned a2, unsigned a3,
                                         unsigned b0, unsigned b1) {
    asm volatile("mma.sync.aligned.m16n8k16.row.col.f32.bf16.bf16.f32 "
                 "{%0,%1,%2,%3}, {%4,%5,%6,%7}, {%8,%9}, {%0,%1,%2,%3};"
                 : "+f"(d[0]), "+f"(d[1]), "+f"(d[2]), "+f"(d[3])
                 : "r"(a0), "r"(a1), "r"(a2), "r"(a3), "r"(b0), "r"(b1));
}

__device__ __forceinline__ unsigned pack2u(unsigned short a, unsigned short b) {
    return (unsigned)a | ((unsigned)b << 16);
}
__device__ __forceinline__ void split1(float x, unsigned short &h, unsigned short &l) {
    __nv_bfloat16 hb = __float2bfloat16(x);
    float r = x - __bfloat162float(hb);
    __nv_bfloat16 lb = __float2bfloat16(r);
    h = *(unsigned short*)&hb;
    l = *(unsigned short*)&lb;
}
__device__ __forceinline__ void cvt8(float4 a, float4 b, uint4 &hw, uint4 &lw) {
    unsigned short h[8], l[8];
    split1(a.x, h[0], l[0]); split1(a.y, h[1], l[1]);
    split1(a.z, h[2], l[2]); split1(a.w, h[3], l[3]);
    split1(b.x, h[4], l[4]); split1(b.y, h[5], l[5]);
    split1(b.z, h[6], l[6]); split1(b.w, h[7], l[7]);
    hw.x = pack2u(h[0], h[1]); hw.y = pack2u(h[2], h[3]);
    hw.z = pack2u(h[4], h[5]); hw.w = pack2u(h[6], h[7]);
    lw.x = pack2u(l[0], l[1]); lw.y = pack2u(l[2], l[3]);
    lw.z = pack2u(l[4], l[5]); lw.w = pack2u(l[6], l[7]);
}

// C = act(A[M,K] @ B[K,N] + bias); B preconverted to hi/lo bf16.
// Block tile 128x128, 8 warps (warp tile 64m x 32n), BK=16, double-buffered.
// K % 16 == 0, N % 128 == 0; M guarded.
template <int ACT>
__global__ __launch_bounds__(256) void k_gemm_t(
    const float* __restrict__ A, const __nv_bfloat16* __restrict__ BH,
    const __nv_bfloat16* __restrict__ BL, const float* __restrict__ bias,
    float* __restrict__ C, int M, int K, int N)
{
    __shared__ __align__(16) unsigned ASh[2][1024];
    __shared__ __align__(16) unsigned ASl[2][1024];
    __shared__ __align__(16) unsigned BSh[2][1024];
    __shared__ __align__(16) unsigned BSl[2][1024];

    const int tid = threadIdx.x, lane = tid & 31, w = tid >> 5;
    const int warpM = w & 1, warpN = w >> 1;     // 2 x 4 warps
    const int bm = blockIdx.x * 128, bn = blockIdx.y * 128;

    // A staging: thread -> (m = tid>>1, k-half h = tid&1)
    const int am = tid >> 1, ah = tid & 1;
    const bool aok = (bm + am) < M;
    const float* aptr = A + (size_t)(bm + am) * K + ah * 8;
    const int ap4 = (ah * 8 + (am & 7) + ((am >> 3) << 4)) * 4;   // word offset

    // B staging: thread -> (k = tid>>4, 8-col chunk c = tid&15)
    const int bk = tid >> 4, bc = tid & 15;
    const __nv_bfloat16* bhp = BH + (size_t)bk * N + bn + bc * 8;
    const __nv_bfloat16* blp = BL + (size_t)bk * N + bn + bc * 8;
    const int bp4 = (bk * 16 + (bc ^ (bk & 7))) * 4;

    float d[4][4][4];
    #pragma unroll
    for (int i = 0; i < 4; i++)
        #pragma unroll
        for (int j = 0; j < 4; j++)
            #pragma unroll
            for (int q = 0; q < 4; q++) d[i][j][q] = 0.f;

    const int nk = K >> 4;
    const float4 z4 = make_float4(0.f, 0.f, 0.f, 0.f);
    float4 av0, av1; uint4 bh4, bl4;

    // prologue: kt = 0
    av0 = aok ? *(const float4*)(aptr)     : z4;
    av1 = aok ? *(const float4*)(aptr + 4) : z4;
    bh4 = *(const uint4*)(bhp);
    bl4 = *(const uint4*)(blp);
    {
        uint4 hw, lw; cvt8(av0, av1, hw, lw);
        *(uint4*)&ASh[0][ap4] = hw; *(uint4*)&ASl[0][ap4] = lw;
        *(uint4*)&BSh[0][bp4] = bh4; *(uint4*)&BSl[0][bp4] = bl4;
    }

    for (int kt = 0; kt < nk; kt++) {
        __syncthreads();
        const int cur = kt & 1;
        // issue next-tile loads (overlap with compute)
        if (kt + 1 < nk) {
            const float* ap = aptr + (kt + 1) * 16;
            av0 = aok ? *(const float4*)(ap)     : z4;
            av1 = aok ? *(const float4*)(ap + 4) : z4;
            bh4 = *(const uint4*)(bhp + (size_t)(kt + 1) * 16 * N);
            bl4 = *(const uint4*)(blp + (size_t)(kt + 1) * 16 * N);
        }

        unsigned baseAh = (unsigned)__cvta_generic_to_shared(&ASh[cur][0]);
        unsigned baseAl = (unsigned)__cvta_generic_to_shared(&ASl[cur][0]);
        unsigned baseBh = (unsigned)__cvta_generic_to_shared(&BSh[cur][0]);
        unsigned baseBl = (unsigned)__cvta_generic_to_shared(&BSl[cur][0]);

        // B fragments (4 n8-tiles, hi + lo)
        unsigned bhf[4][2], blf[4][2];
        {
            int kk = lane & 15;
            #pragma unroll
            for (int nt = 0; nt < 4; nt++) {
                int c = warpN * 4 + nt;
                unsigned off = (unsigned)(kk * 256 + ((c ^ (kk & 7)) << 4));
                ldsm_x2t(baseBh + off, bhf[nt][0], bhf[nt][1]);
                ldsm_x2t(baseBl + off, blf[nt][0], blf[nt][1]);
            }
        }
        // A fragments + mma (4 m16-tiles)
        #pragma unroll
        for (int mt = 0; mt < 4; mt++) {
            int m = warpM * 64 + mt * 16 + (lane & 7) + ((lane >> 3) & 1) * 8;
            int h = (lane >> 4) & 1;
            unsigned off = (unsigned)((h * 8 + (m & 7) + ((m >> 3) << 4)) << 4);
            unsigned a0, a1, a2, a3, l0, l1, l2, l3;
            ldsm_x4(baseAh + off, a0, a1, a2, a3);
            ldsm_x4(baseAl + off, l0, l1, l2, l3);
            #pragma unroll
            for (int nt = 0; nt < 4; nt++) {
                mma_bf16(d[mt][nt], a0, a1, a2, a3, bhf[nt][0], bhf[nt][1]);
                mma_bf16(d[mt][nt], a0, a1, a2, a3, blf[nt][0], blf[nt][1]);
                mma_bf16(d[mt][nt], l0, l1, l2, l3, bhf[nt][0], bhf[nt][1]);
            }
        }
        // stage next tile into the other buffer
        if (kt + 1 < nk) {
            uint4 hw, lw; cvt8(av0, av1, hw, lw);
            int nxt = cur ^ 1;
            *(uint4*)&ASh[nxt][ap4] = hw; *(uint4*)&ASl[nxt][ap4] = lw;
            *(uint4*)&BSh[nxt][bp4] = bh4; *(uint4*)&BSl[nxt][bp4] = bl4;
        }
    }

    // epilogue
    const int gid = lane >> 2, tig = lane & 3;
    #pragma unroll
    for (int mt = 0; mt < 4; mt++) {
        int r0 = bm + warpM * 64 + mt * 16 + gid;
        int r1 = r0 + 8;
        #pragma unroll
        for (int nt = 0; nt < 4; nt++) {
            int cc = bn + warpN * 32 + nt * 8 + tig * 2;
            float b0v = bias ? bias[cc] : 0.f;
            float b1v = bias ? bias[cc + 1] : 0.f;
            if (r0 < M) {
                float v0 = d[mt][nt][0] + b0v, v1 = d[mt][nt][1] + b1v;
                if (ACT == 1) { v0 = fmaxf(v0, 0.f); v1 = fmaxf(v1, 0.f); }
                C[(size_t)r0 * N + cc] = v0; C[(size_t)r0 * N + cc + 1] = v1;
            }
            if (r1 < M) {
                float v2 = d[mt][nt][2] + b0v, v3 = d[mt][nt][3] + b1v;
                if (ACT == 1) { v2 = fmaxf(v2, 0.f); v3 = fmaxf(v3, 0.f); }
                C[(size_t)r1 * N + cc] = v2; C[(size_t)r1 * N + cc + 1] = v3;
            }
        }
    }
}

// ---------------- Attention logits: per (node, head) dots ----------------
template <int H, int C>
__global__ __launch_bounds__(256) void k_alpha(const float* __restrict__ p,
                                               const float* __restrict__ a_s,
                                               const float* __restrict__ a_d) {
    int w = (blockIdx.x * blockDim.x + threadIdx.x) >> 5;
    int lane = threadIdx.x & 31;
    if (w >= NNODES * H) return;
    int node = w / H, h = w - node * H;
    const float* row = p + (size_t)node * (H * C) + h * C;
    float vs = 0.f, vd = 0.f;
    #pragma unroll
    for (int k = lane; k < C; k += 32) {
        float v = row[k];
        vs = fmaf(v, a_s[h * C + k], vs);
        vd = fmaf(v, a_d[h * C + k], vd);
    }
    #pragma unroll
    for (int o = 16; o; o >>= 1) {
        vs += __shfl_xor_sync(0xffffffffu, vs, o);
        vd += __shfl_xor_sync(0xffffffffu, vd, o);
    }
    if (lane == 0) { g_as[w] = vs; g_ad[w] = vd; }
}

// ---------------- GAT aggregation (one block per destination node) ---------
template <int H, int C, bool CONCAT, bool ELU>
__global__ __launch_bounds__(H * C) void k_gat_agg(const float* __restrict__ p,
                                                   const float* __restrict__ bias,
                                                   float* __restrict__ out) {
    constexpr int HC = H * C;
    constexpr int V = HC / 4;
    constexpr int GROUPS = 4;
    constexpr int CHUNK = 32;
    __shared__ int   s_src[CHUNK];
    __shared__ float s_w[CHUNK * H];
    __shared__ float s_m[H];
    __shared__ float s_den[H];
    __shared__ float s_adv[H];
    __shared__ __align__(16) float s_red[GROUPS * HC];

    int node = blockIdx.x;
    int tid = threadIdx.x;
    int beg = g_off[node], end = g_off[node + 1];
    int w = tid >> 5, lane = tid & 31;

    if (tid < H) s_adv[tid] = g_ad[node * H + tid];
    __syncthreads();

    if (w < H) {
        float ad_h = s_adv[w];
        float m_l = -1e30f, d_l = 0.f;
        for (int e = beg + lane; e < end; e += 32) {
            float z = g_as[g_srcs[e] * H + w] + ad_h;
            z = (z > 0.f) ? z : NEG_SLOPE * z;
            float mo = fmaxf(m_l, z);
            d_l = d_l * __expf(m_l - mo) + __expf(z - mo);
            m_l = mo;
        }
        #pragma unroll
        for (int o = 16; o; o >>= 1) {
            float m2 = __shfl_xor_sync(0xffffffffu, m_l, o);
            float d2 = __shfl_xor_sync(0xffffffffu, d_l, o);
            float mo = fmaxf(m_l, m2);
            d_l = d_l * __expf(m_l - mo) + d2 * __expf(m2 - mo);
            m_l = mo;
        }
        if (lane == 0) { s_m[w] = m_l; s_den[w] = d_l + EPSV; }
    }
    __syncthreads();

    const int grp = tid / V;
    const int q   = tid - grp * V;
    const int h_of = (4 * q) / C;
    float4 acc = make_float4(0.f, 0.f, 0.f, 0.f);

    for (int cb = beg; cb < end; cb += CHUNK) {
        int len = min(CHUNK, end - cb);
        if (tid < len) s_src[tid] = g_srcs[cb + tid];
        __syncthreads();
        if (tid < len * H) {
            int e_i = tid / H, h = tid - e_i * H;
            int s = s_src[e_i];
            float z = g_as[s * H + h] + s_adv[h];
            z = (z > 0.f) ? z : NEG_SLOPE * z;
            s_w[tid] = __expf(z - s_m[h]) / s_den[h];
        }
        __syncthreads();
        int e = grp;
        for (; e + GROUPS < len; e += 2 * GROUPS) {
            int s0 = s_src[e], s1 = s_src[e + GROUPS];
            float4 v0 = *(const float4*)&p[(size_t)s0 * HC + 4 * q];
            float4 v1 = *(const float4*)&p[(size_t)s1 * HC + 4 * q];
            float w0 = s_w[e * H + h_of];
            float w1 = s_w[(e + GROUPS) * H + h_of];
            acc.x = fmaf(v0.x, w0, acc.x); acc.y = fmaf(v0.y, w0, acc.y);
            acc.z = fmaf(v0.z, w0, acc.z); acc.w = fmaf(v0.w, w0, acc.w);
            acc.x = fmaf(v1.x, w1, acc.x); acc.y = fmaf(v1.y, w1, acc.y);
            acc.z = fmaf(v1.z, w1, acc.z); acc.w = fmaf(v1.w, w1, acc.w);
        }
        if (e < len) {
            int s0 = s_src[e];
            float4 v0 = *(const float4*)&p[(size_t)s0 * HC + 4 * q];
            float w0 = s_w[e * H + h_of];
            acc.x = fmaf(v0.x, w0, acc.x); acc.y = fmaf(v0.y, w0, acc.y);
            acc.z = fmaf(v0.z, w0, acc.z); acc.w = fmaf(v0.w, w0, acc.w);
        }
        __syncthreads();
    }

    *(float4*)&s_red[grp * HC + 4 * q] = acc;
    __syncthreads();

    if (CONCAT) {
        float v = 0.f;
        #pragma unroll
        for (int g = 0; g < GROUPS; g++) v += s_red[g * HC + tid];
        v += bias[tid];
        if (ELU) v = (v > 0.f) ? v : expm1f(v);
        out[(size_t)node * HC + tid] = v;
    } else {
        if (tid < C) {
            float v = 0.f;
            #pragma unroll
            for (int g = 0; g < GROUPS; g++)
                #pragma unroll
                for (int h = 0; h < H; h++)
                    v += s_red[g * HC + h * C + tid];
            v = v * (1.f / H) + bias[tid];
            if (ELU) v = (v > 0.f) ? v : expm1f(v);
            out[(size_t)node * C + tid] = v;
        }
    }
}

// ---------------- Launch ----------------
extern "C" void kernel_launch(void* const* d_in, const int* in_sizes, int n_in,
                              void* d_out, int out_size) {
    const float* x     = (const float*)d_in[0];
    const void*  ei    = d_in[1];
    const float* W1    = (const float*)d_in[2];
    const float* b1    = (const float*)d_in[3];
    const float* W2    = (const float*)d_in[4];
    const float* b2    = (const float*)d_in[5];
    const float* g1W   = (const float*)d_in[6];
    const float* g1as  = (const float*)d_in[7];
    const float* g1ad  = (const float*)d_in[8];
    const float* g1b   = (const float*)d_in[9];
    const float* g2W   = (const float*)d_in[10];
    const float* g2as  = (const float*)d_in[11];
    const float* g2ad  = (const float*)d_in[12];
    const float* g2b   = (const float*)d_in[13];
    const float* g3W   = (const float*)d_in[14];
    const float* g3as  = (const float*)d_in[15];
    const float* g3ad  = (const float*)d_in[16];
    const float* g3b   = (const float*)d_in[17];
    float* out = (float*)d_out;

    float* bufA; float* bufB; __nv_bfloat16* wh; __nv_bfloat16* wl;
    cudaGetSymbolAddress((void**)&bufA, g_bufA);
    cudaGetSymbolAddress((void**)&bufB, g_bufB);
    cudaGetSymbolAddress((void**)&wh,   g_wh);
    cudaGetSymbolAddress((void**)&wl,   g_wl);

    const int M = NNODES;
    const int E = in_sizes[1] / 2;

    // ---- Weight preconversion ----
    k_cvtw<<<(32768 + 255) / 256, 256>>>(W1,  wh + OFF_W1, wl + OFF_W1, 32768);
    k_cvtw<<<(16384 + 255) / 256, 256>>>(W2,  wh + OFF_W2, wl + OFF_W2, 16384);
    k_cvtw<<<(32768 + 255) / 256, 256>>>(g1W, wh + OFF_G1, wl + OFF_G1, 32768);
    k_cvtw<<<(65536 + 255) / 256, 256>>>(g2W, wh + OFF_G2, wl + OFF_G2, 65536);
    k_cvtw<<<(16384 + 255) / 256, 256>>>(g3W, wh + OFF_G3, wl + OFF_G3, 16384);

    // ---- CSR build (by destination) ----
    k_reset<<<(M + 255) / 256, 256>>>(M);
    k_detect<<<(E + 255) / 256, 256>>>((const long long*)ei, E);
    k_count<<<(E + 255) / 256, 256>>>(ei, E);
    k_scan1<<<NPART, 1024>>>(M);
    k_scan2<<<1, 64>>>();
    k_scan3<<<NPART, 1024>>>(M);
    k_scatter<<<(E + M + 255) / 256, 256>>>(ei, E, M);

    dim3 blk(256);
    const int GM = (M + 127) / 128;
    // ---- MLP ----
    { dim3 g(GM, 1);
      k_gemm_t<1><<<g, blk>>>(x, wh + OFF_W1, wl + OFF_W1, b1, bufA, M, DIN, DHID); }
    { dim3 g(GM, 1);
      k_gemm_t<1><<<g, blk>>>(bufA, wh + OFF_W2, wl + OFF_W2, b2, bufB, M, DHID, DHID); }

    // ---- GAT layer 1: H=4, C=64, concat, elu ----
    { dim3 g(GM, 2);
      k_gemm_t<0><<<g, blk>>>(bufB, wh + OFF_G1, wl + OFF_G1, nullptr, bufA, M, DHID, 256); }
    k_alpha<4, 64><<<(M * 4 * 32 + 255) / 256, 256>>>(bufA, g1as, g1ad);
    k_gat_agg<4, 64, true, true><<<M, 256>>>(bufA, g1b, bufB);

    // ---- GAT layer 2: H=2, C=128, mean, elu ----
    { dim3 g(GM, 2);
      k_gemm_t<0><<<g, blk>>>(bufB, wh + OFF_G2, wl + OFF_G2, nullptr, bufA, M, 256, 256); }
    k_alpha<2, 128><<<(M * 2 * 32 + 255) / 256, 256>>>(bufA, g2as, g2ad);
    k_gat_agg<2, 128, false, true><<<M, 256>>>(bufA, g2b, bufB);

    // ---- GAT layer 3: H=1, C=128, mean (identity), no elu ----
    { dim3 g(GM, 1);
      k_gemm_t<0><<<g, blk>>>(bufB, wh + OFF_G3, wl + OFF_G3, nullptr, bufA, M, DOUT, DOUT); }
    k_alpha<1, 128><<<(M * 1 * 32 + 255) / 256, 256>>>(bufA, g3as, g3ad);
    k_gat_agg<1, 128, false, false><<<M, 128>>>(bufA, g3b, out);
}